// round 10
// baseline (speedup 1.0000x reference)
#include <cuda_runtime.h>
#include <math.h>

#define NG 8
#define GS 16
#define BR 32
#define TT 512
#define NTH 256

__device__ float g_A[NG][256*BR];
__device__ float g_NOS[NG][64*BR];
__device__ float g_HD[NG][256*BR];
__device__ float g_OBS[NG][64*BR];
__device__ float g_NH0[2][NG][128*BR];
__device__ float g_NH1[2][NG][128*BR];
__device__ unsigned g_ctr[NG];

#define OMUS  0L
#define OSTDS 8388608L
#define ORETS 16777216L
#define OFIN  58720256L

// smem float offsets
#define O_WT1 0
#define O_WT2 1200
#define O_WMS 2228
#define O_WD 4284
#define O_WRZ0 8556
#define O_WIN0 12828
#define O_WHN0 13940
#define O_WRZ1 14972
#define O_WIN1 19084
#define O_WHN1 20116
#define O_B1 21148
#define O_B2 21164
#define O_BS3 21168
#define O_BS4 21200
#define O_BD 21232
#define O_BMS 21248
#define O_ACT 21256
#define O_PART 29768
#define O_SCR 31816
#define O_SEQ 32840
#define SMEM_BYTES (32872*4)

__device__ __forceinline__ void bar(int g, unsigned tgt) {
    __syncthreads();
    __threadfence();
    if (threadIdx.x == 0) {
        atomicAdd(&g_ctr[g], 1u);
        volatile unsigned* p = &g_ctr[g];
        while (*p < tgt) __nanosleep(64);
        __threadfence();
    }
    __syncthreads();
}

// generic matvec: NCG col-groups x CB cols each, KP k-partitions (NCG*KP==32)
template<int NCG,int CB,int KP,int TH>
__device__ __forceinline__ void mv(const float* __restrict__ w, int ldw, int K,
    const float* __restrict__ act, const float* __restrict__ bias,
    float* part, float* dst) {
    const int tid = threadIdx.x, rq = tid & 7, s = tid >> 3;
    const int cg = s % NCG, p = s / NCG;
    const int k0 = p * K / KP, k1 = (p + 1) * K / KP;
    const float* wc = w + cg * CB * ldw;
    float4 acc[CB];
#pragma unroll
    for (int j = 0; j < CB; j++) acc[j] = make_float4(0.f,0.f,0.f,0.f);
    __syncthreads();
    const float* ap = act + rq * 4;
#pragma unroll 2
    for (int k = k0; k < k1; k++) {
        float4 x = *(const float4*)(ap + k * 32);
#pragma unroll
        for (int j = 0; j < CB; j++) {
            float wv = wc[j * ldw + k];
            acc[j].x = fmaf(wv,x.x,acc[j].x); acc[j].y = fmaf(wv,x.y,acc[j].y);
            acc[j].z = fmaf(wv,x.z,acc[j].z); acc[j].w = fmaf(wv,x.w,acc[j].w);
        }
    }
#pragma unroll
    for (int j = 0; j < CB; j++) *(float4*)(part + (s*CB+j)*32 + rq*4) = acc[j];
    __syncthreads();
    for (int o = tid; o < NCG*CB*32; o += NTH) {
        int c2 = o >> 5, r = o & 31, cg2 = c2 / CB, j = c2 % CB;
        float v = bias[c2];
#pragma unroll
        for (int q = 0; q < KP; q++) v += part[((q*NCG+cg2)*CB+j)*32 + r];
        dst[o] = TH ? tanhf(v) : v;
    }
    __syncthreads();
}

// fused GRU dot: cols 0-15 rz (K=Kx+128), 16-23 in (K=Kx), 24-31 hn (K=128)
__device__ __forceinline__ void grudot(const float* __restrict__ wrz, int ldrz,
    const float* __restrict__ win, int ldin, const float* __restrict__ whn,
    int Kx, const float* __restrict__ act, const float* __restrict__ bias,
    float* part, float* scr) {
    const int tid = threadIdx.x, rq = tid & 7, s = tid >> 3;
    const int cg = s & 15, p = s >> 4;
    const float* wc; int K, ao, ld;
    if (cg < 8)       { wc = wrz + cg*2*ldrz;      K = Kx+128; ao = 0;     ld = ldrz; }
    else if (cg < 12) { wc = win + (cg-8)*2*ldin;  K = Kx;     ao = 0;     ld = ldin; }
    else              { wc = whn + (cg-12)*2*129;  K = 128;    ao = Kx*32; ld = 129;  }
    const int k0 = p * K / 2, k1 = (p + 1) * K / 2;
    float4 a0 = make_float4(0.f,0.f,0.f,0.f), a1 = a0;
    __syncthreads();
    const float* ap = act + ao + rq * 4;
    for (int k = k0; k < k1; k++) {
        float4 x = *(const float4*)(ap + k * 32);
        float w0 = wc[k], w1 = wc[ld + k];
        a0.x=fmaf(w0,x.x,a0.x); a0.y=fmaf(w0,x.y,a0.y); a0.z=fmaf(w0,x.z,a0.z); a0.w=fmaf(w0,x.w,a0.w);
        a1.x=fmaf(w1,x.x,a1.x); a1.y=fmaf(w1,x.y,a1.y); a1.z=fmaf(w1,x.z,a1.z); a1.w=fmaf(w1,x.w,a1.w);
    }
    *(float4*)(part + (s*2)*32 + rq*4) = a0;
    *(float4*)(part + (s*2+1)*32 + rq*4) = a1;
    __syncthreads();
    for (int o = tid; o < 1024; o += NTH) {
        int c2 = o >> 5, r = o & 31, cg2 = c2 >> 1, j = c2 & 1;
        scr[o] = bias[c2] + part[(cg2*2+j)*32 + r] + part[((16+cg2)*2+j)*32 + r];
    }
    __syncthreads();
}

__device__ __forceinline__ void cpx(float* d, const float* s, int kc) {
    const float4* s4 = (const float4*)s; float4* d4 = (float4*)d;
    for (int i = threadIdx.x; i < kc*8; i += NTH) d4[i] = __ldcg(s4 + i);
}
__device__ __forceinline__ void cpx_mask(float* d, const float* s, int kc,
                                         const int* sq, int tp) {
    const float4* s4 = (const float4*)s; float4* d4 = (float4*)d;
    for (int i = threadIdx.x; i < kc*8; i += NTH) {
        float4 v = __ldcg(s4 + i); int r = (i & 7) * 4;
        if (tp >= sq[r+0]) v.x = 0.f; if (tp >= sq[r+1]) v.y = 0.f;
        if (tp >= sq[r+2]) v.z = 0.f; if (tp >= sq[r+3]) v.w = 0.f;
        d4[i] = v;
    }
}
__device__ __forceinline__ void cpt4(float* d, const float* s, int rs, int K) {
    int K4 = K >> 2;
    for (int i = threadIdx.x; i < K4*BR; i += NTH) {
        int kq = i % K4, r = i / K4;
        float4 v = *(const float4*)(s + (size_t)r*rs + kq*4);
        d[(kq*4+0)*32+r]=v.x; d[(kq*4+1)*32+r]=v.y;
        d[(kq*4+2)*32+r]=v.z; d[(kq*4+3)*32+r]=v.w;
    }
}
__device__ __forceinline__ void cpt2(float* d, const float* s, int rs, int K) {
    int K2 = K >> 1;
    for (int i = threadIdx.x; i < K2*BR; i += NTH) {
        int kq = i % K2, r = i / K2;
        float2 v = *(const float2*)(s + (size_t)r*rs + kq*2);
        d[(kq*2+0)*32+r]=v.x; d[(kq*2+1)*32+r]=v.y;
    }
}
__device__ __forceinline__ void ldT(float* d,int ldw,int K,const float* s,int N,int c0,int nc){
    for (int i = threadIdx.x; i < nc*ldw; i += NTH) {
        int c = i / ldw, k = i % ldw;
        d[i] = (k < K) ? s[k*N + c0 + c] : 0.f;
    }
}
__device__ __forceinline__ void ldN(float* d,int ldw,int K,const float* s,int c0,int nc){
    for (int i = threadIdx.x; i < nc*ldw; i += NTH) {
        int c = i / ldw, k = i % ldw;
        d[i] = (k < K) ? s[(c0+c)*K + k] : 0.f;
    }
}
__device__ __forceinline__ void ldRZ(float* d,int ldw,const float* wih,int Kx,
                                     const float* whh,int ct){
    for (int i = threadIdx.x; i < 16*ldw; i += NTH) {
        int c = i / ldw, k = i % ldw;
        int j = (c < 8) ? ct*8 + c : 128 + ct*8 + (c - 8);
        d[i] = (k < Kx) ? wih[j*Kx + k] : ((k < Kx+128) ? whh[j*128 + (k-Kx)] : 0.f);
    }
}
__device__ __forceinline__ float sigf(float x){ return 1.f/(1.f+expf(-x)); }

__global__ void dynarnn_init() { if (threadIdx.x < NG) g_ctr[threadIdx.x] = 0u; }

__global__ void __launch_bounds__(NTH,1)
dynarnn_main(const float* __restrict__ obp, const float* __restrict__ acp,
             const float* __restrict__ noisep, const float* __restrict__ prevp,
             const int* __restrict__ seqp,
             const float* __restrict__ Wih0, const float* __restrict__ Whh0,
             const float* __restrict__ bih0, const float* __restrict__ bhh0,
             const float* __restrict__ Wih1, const float* __restrict__ Whh1,
             const float* __restrict__ bih1, const float* __restrict__ bhh1,
             const float* __restrict__ Wt1p, const float* __restrict__ bt1p,
             const float* __restrict__ Wt2p, const float* __restrict__ bt2p,
             const float* __restrict__ Wd1p, const float* __restrict__ bd1p,
             const float* __restrict__ Wmup, const float* __restrict__ bmup,
             const float* __restrict__ Wsdp, const float* __restrict__ bsdp,
             float* __restrict__ out)
{
    extern __shared__ float sm[];
    const int tid = threadIdx.x;
    const int g = blockIdx.x >> 4, ct = blockIdx.x & 15;
    float *wt1 = sm+O_WT1, *wt2 = sm+O_WT2, *wms = sm+O_WMS, *wd = sm+O_WD;
    float *wrz0 = sm+O_WRZ0, *win0 = sm+O_WIN0, *whn0 = sm+O_WHN0;
    float *wrz1 = sm+O_WRZ1, *win1 = sm+O_WIN1, *whn1 = sm+O_WHN1;
    float *b1 = sm+O_B1, *b2 = sm+O_B2, *bS3 = sm+O_BS3, *bS4 = sm+O_BS4;
    float *bd = sm+O_BD, *bms = sm+O_BMS;
    float *sAct = sm+O_ACT, *part = sm+O_PART, *scr = sm+O_SCR;
    int *sseq = (int*)(sm+O_SEQ);

    ldT(wt1, 75, 74, Wt1p, 256, ct*16, 16);
    ldT(wt2, 257, 256, Wt2p, 64, ct*4, 4);
    ldT(wms, 257, 256, Wmup, 64, ct*4, 4);
    ldT(wms + 4*257, 257, 256, Wsdp, 64, ct*4, 4);
    ldT(wd, 267, 266, Wd1p, 256, ct*16, 16);
    ldRZ(wrz0, 267, Wih0, 138, Whh0, ct);
    ldRZ(wrz1, 257, Wih1, 128, Whh1, ct);
    ldN(win0, 139, 138, Wih0, 256 + ct*8, 8);
    ldN(whn0, 129, 128, Whh0, 256 + ct*8, 8);
    ldN(win1, 129, 128, Wih1, 256 + ct*8, 8);
    ldN(whn1, 129, 128, Whh1, 256 + ct*8, 8);
    if (tid < 16) {
        b1[tid] = bt1p[ct*16 + tid]; bd[tid] = bd1p[ct*16 + tid];
        int j = (tid < 8) ? ct*8 + tid : 128 + ct*8 + tid - 8;
        bS3[tid] = bih0[j] + bhh0[j]; bS4[tid] = bih1[j] + bhh1[j];
    } else if (tid < 32) {
        int q = tid - 16, j = 256 + ct*8 + (q & 7);
        if (q < 8) { bS3[tid] = bih0[j]; bS4[tid] = bih1[j]; }
        else       { bS3[tid] = bhh0[j]; bS4[tid] = bhh1[j]; }
    }
    if (tid < 4) { b2[tid] = bt2p[ct*4+tid]; bms[tid] = bmup[ct*4+tid]; bms[4+tid] = bsdp[ct*4+tid]; }
    if (tid < BR) sseq[tid] = seqp[g*BR + tid];
    // init carries (disjoint slices per CTA)
    for (int i = tid; i < 8*32; i += NTH) {
        int kk = i >> 5, r = i & 31, k = ct*8 + kk;
        const float* pv = prevp + (size_t)(g*BR + r) * 320;
        g_NH0[0][g][k*32 + r] = pv[k];
        g_NH1[0][g][k*32 + r] = pv[128 + k];
        if (kk < 4) { int k2 = ct*4 + kk; g_OBS[g][k2*32 + r] = pv[256 + k2]; }
    }
    unsigned nb = 1;
    bar(g, GS*nb); nb++;

    for (int t = 0; t < TT; t++) {
        float* nh0rd = g_NH0[t&1][g];       float* nh0wr = g_NH0[(t&1)^1][g];
        float* nh1rd = g_NH1[t&1][g];       float* nh1wr = g_NH1[(t&1)^1][g];
        const float* obT = obp + (size_t)g*BR*TT*64 + (size_t)t*64;
        const float* acT = acp + (size_t)g*BR*TT*10 + (size_t)t*10;
        // S1: a = tanh([obs, ac] @ Wt1 + bt1)
        cpx(sAct, g_OBS[g], 64);
        cpt2(sAct + 64*32, acT, TT*10, 10);
        mv<8,2,4,1>(wt1, 75, 74, sAct, b1, part, g_A[g] + ct*16*32);
        bar(g, GS*nb); nb++;
        // S2: nos = a @ Wt2 + bt2
        cpx(sAct, g_A[g], 256);
        mv<2,2,16,0>(wt2, 257, 256, sAct, b2, part, g_NOS[g] + ct*4*32);
        bar(g, GS*nb); nb++;
        // S3: GRU0, x=[ob,nos,ac](138), h=mask(t-1)*nh0
        cpt4(sAct, obT, TT*64, 64);
        cpx(sAct + 64*32, g_NOS[g], 64);
        cpt2(sAct + 128*32, acT, TT*10, 10);
        cpx_mask(sAct + 138*32, nh0rd, 128, sseq, t - 1);
        grudot(wrz0, 267, win0, 139, whn0, 138, sAct, bS3, part, scr);
        {
            int c = tid >> 5, r = tid & 31, cg2 = ct*8 + c;
            float rg = sigf(scr[c*32 + r]);
            float zg = sigf(scr[(8+c)*32 + r]);
            float ng = tanhf(scr[(16+c)*32 + r] + rg * scr[(24+c)*32 + r]);
            float hp = sAct[(138 + cg2)*32 + r];
            float nh = (1.f - zg)*ng + zg*hp;
            nh0wr[cg2*32 + r] = nh;                    // unmasked: GRU1 input
            float hm = (t < sseq[r]) ? nh : 0.f;
            size_t b = (size_t)(g*BR + r);
            out[ORETS + (b*TT + t)*320 + cg2] = hm;
            if (t == TT-1) out[OFIN + b*320 + cg2] = hm;
        }
        bar(g, GS*nb); nb++;
        // S4: GRU1, x=nh0(unmasked), h=nh1(masked)
        cpx(sAct, nh0wr, 128);
        cpx(sAct + 128*32, nh1rd, 128);
        grudot(wrz1, 257, win1, 129, whn1, 128, sAct, bS4, part, scr);
        {
            int c = tid >> 5, r = tid & 31, cg2 = ct*8 + c;
            float rg = sigf(scr[c*32 + r]);
            float zg = sigf(scr[(8+c)*32 + r]);
            float ng = tanhf(scr[(16+c)*32 + r] + rg * scr[(24+c)*32 + r]);
            float hp = sAct[(128 + cg2)*32 + r];
            float nh = (1.f - zg)*ng + zg*hp;
            float hm = (t < sseq[r]) ? nh : 0.f;
            nh1wr[cg2*32 + r] = hm;                    // masked carry = out
            size_t b = (size_t)(g*BR + r);
            out[ORETS + (b*TT + t)*320 + 128 + cg2] = hm;
            if (t == TT-1) out[OFIN + b*320 + 128 + cg2] = hm;
        }
        bar(g, GS*nb); nb++;
        // S5: hdec = tanh([out, nos, ob, ac] @ Wd1 + bd1)
        cpx(sAct, nh1wr, 128);
        cpx(sAct + 128*32, g_NOS[g], 64);
        cpt4(sAct + 192*32, obT, TT*64, 64);
        cpt2(sAct + 256*32, acT, TT*10, 10);
        mv<8,2,4,1>(wd, 267, 266, sAct, bd, part, g_HD[g] + ct*16*32);
        bar(g, GS*nb); nb++;
        // S6: mu/std/ob_sim
        cpx(sAct, g_HD[g], 256);
        mv<4,2,8,0>(wms, 257, 256, sAct, bms, part, scr);
        if (tid < 128) {
            int c = tid >> 5, r = tid & 31, cgl = ct*4 + c;
            float mu = scr[c*32 + r];
            float sv = scr[(4+c)*32 + r];
            float sd = fmaxf(sv, 0.f) + log1pf(expf(-fabsf(sv))) + 1e-4f;
            size_t b = (size_t)(g*BR + r);
            float eps = noisep[(b*TT + t)*64 + cgl];
            float obs = fmaf(sd, eps, mu);
            g_OBS[g][cgl*32 + r] = obs;
            out[OMUS  + (b*TT + t)*64 + cgl] = mu;
            out[OSTDS + (b*TT + t)*64 + cgl] = sd;
            out[ORETS + (b*TT + t)*320 + 256 + cgl] = obs;
            if (t == TT-1) out[OFIN + b*320 + 256 + cgl] = obs;
        }
        bar(g, GS*nb); nb++;
    }
}

extern "C" void kernel_launch(void* const* d_in, const int* in_sizes, int n_in,
                              void* d_out, int out_size) {
    cudaFuncSetAttribute(dynarnn_main, cudaFuncAttributeMaxDynamicSharedMemorySize, SMEM_BYTES);
    dynarnn_init<<<1, 32>>>();
    dynarnn_main<<<NG*GS, NTH, SMEM_BYTES>>>(
        (const float*)d_in[0], (const float*)d_in[1], (const float*)d_in[2],
        (const float*)d_in[3], (const int*)d_in[4],
        (const float*)d_in[5], (const float*)d_in[6], (const float*)d_in[7],
        (const float*)d_in[8], (const float*)d_in[9], (const float*)d_in[10],
        (const float*)d_in[11], (const float*)d_in[12],
        (const float*)d_in[13], (const float*)d_in[14], (const float*)d_in[15],
        (const float*)d_in[16], (const float*)d_in[17], (const float*)d_in[18],
        (const float*)d_in[19], (const float*)d_in[20], (const float*)d_in[21],
        (const float*)d_in[22], (float*)d_out);
}

// round 11
// speedup vs baseline: 1.1530x; 1.1530x over previous
#include <cuda_runtime.h>
#include <math.h>

#define NG 8
#define GS 16
#define BR 32
#define TT 512
#define NTH 256
typedef unsigned long long ull;

__device__ float g_A[NG][256*BR];
__device__ float g_NOS[NG][64*BR];
__device__ float g_HD[NG][256*BR];
__device__ float g_OBS[NG][64*BR];
__device__ float g_NH0[2][NG][128*BR];
__device__ float g_NH1[2][NG][128*BR];
__device__ unsigned g_ctr[NG];

#define OMUS  0L
#define OSTDS 8388608L
#define ORETS 16777216L
#define OFIN  58720256L

// smem float offsets
#define O_WT1 0
#define O_WT2 1200
#define O_WMS 2228
#define O_WD 4284
#define O_WRZ0 8556
#define O_WIN0 12828
#define O_WHN0 13940
#define O_WRZ1 14972
#define O_WIN1 19084
#define O_WHN1 20116
#define O_B1 21148
#define O_B2 21164
#define O_BS3 21168
#define O_BS4 21200
#define O_BD 21232
#define O_BMS 21248
#define O_X1 21256
#define O_A 23624
#define O_ACT 31816
#define O_X4 40328
#define O_PART 48520
#define O_SCR 50568
#define O_SEQ 51592
#define SMEM_BYTES (51624*4)

__device__ __forceinline__ ull pk(float w) {
    ull r; asm("mov.b64 %0,{%1,%1};" : "=l"(r) : "f"(w)); return r;
}
__device__ __forceinline__ void fma2(ull& d, ull a, ull b) {
    asm("fma.rn.f32x2 %0,%1,%2,%0;" : "+l"(d) : "l"(a), "l"(b));
}
__device__ __forceinline__ float4 upk(ull lo, ull hi) {
    float4 v; *(ull*)&v.x = lo; *(ull*)&v.z = hi; return v;
}

__device__ __forceinline__ void bar_arrive(int g) {
    __syncthreads();
    __threadfence();
    if (threadIdx.x == 0) atomicAdd(&g_ctr[g], 1u);
}
__device__ __forceinline__ void bar_wait(int g, unsigned tgt) {
    if (threadIdx.x == 0) {
        volatile unsigned* p = &g_ctr[g];
        while (*p < tgt) { }
        __threadfence();
    }
    __syncthreads();
}

// matvec: NCG col-groups x CB cols, KP k-partitions (NCG*KP==32)
template<int NCG,int CB,int KP,int TH>
__device__ __forceinline__ void mv(const float* __restrict__ w, int ldw, int K,
    const float* __restrict__ act, const float* __restrict__ bias,
    float* part, float* dst) {
    const int tid = threadIdx.x, rq = tid & 7, s = tid >> 3;
    const int cg = s % NCG, p = s / NCG;
    const int k0 = p * K / KP, k1 = (p + 1) * K / KP;
    const float* wc = w + cg * CB * ldw;
    ull acc[CB][2];
#pragma unroll
    for (int j = 0; j < CB; j++) { acc[j][0] = 0ull; acc[j][1] = 0ull; }
    __syncthreads();
    const float* ap = act + rq * 4;
#pragma unroll 2
    for (int k = k0; k < k1; k++) {
        ulonglong2 x = *(const ulonglong2*)(ap + k * 32);
#pragma unroll
        for (int j = 0; j < CB; j++) {
            ull wp = pk(wc[j * ldw + k]);
            fma2(acc[j][0], wp, x.x);
            fma2(acc[j][1], wp, x.y);
        }
    }
#pragma unroll
    for (int j = 0; j < CB; j++)
        *(float4*)(part + (s*CB+j)*32 + rq*4) = upk(acc[j][0], acc[j][1]);
    __syncthreads();
    for (int o = tid; o < NCG*CB*32; o += NTH) {
        int c2 = o >> 5, r = o & 31, cg2 = c2 / CB, j = c2 % CB;
        float v = bias[c2];
#pragma unroll
        for (int q = 0; q < KP; q++) v += part[((q*NCG+cg2)*CB+j)*32 + r];
        dst[o] = TH ? tanhf(v) : v;
    }
    __syncthreads();
}

// fused GRU dot: cols 0-15 rz (K=Kx+128), 16-23 in (K=Kx), 24-31 hn (K=128)
__device__ __forceinline__ void grudot(const float* __restrict__ wrz, int ldrz,
    const float* __restrict__ win, int ldin, const float* __restrict__ whn,
    int Kx, const float* __restrict__ act, const float* __restrict__ bias,
    float* part, float* scr) {
    const int tid = threadIdx.x, rq = tid & 7, s = tid >> 3;
    const int cg = s & 15, p = s >> 4;
    const float* wc; int K, ao, ld;
    if (cg < 8)       { wc = wrz + cg*2*ldrz;     K = Kx+128; ao = 0;     ld = ldrz; }
    else if (cg < 12) { wc = win + (cg-8)*2*ldin; K = Kx;     ao = 0;     ld = ldin; }
    else              { wc = whn + (cg-12)*2*129; K = 128;    ao = Kx*32; ld = 129;  }
    const int k0 = p * K / 2, k1 = (p + 1) * K / 2;
    ull a00 = 0ull, a01 = 0ull, a10 = 0ull, a11 = 0ull;
    __syncthreads();
    const float* ap = act + ao + rq * 4;
    for (int k = k0; k < k1; k++) {
        ulonglong2 x = *(const ulonglong2*)(ap + k * 32);
        ull w0 = pk(wc[k]), w1 = pk(wc[ld + k]);
        fma2(a00, w0, x.x); fma2(a01, w0, x.y);
        fma2(a10, w1, x.x); fma2(a11, w1, x.y);
    }
    *(float4*)(part + (s*2)*32 + rq*4)   = upk(a00, a01);
    *(float4*)(part + (s*2+1)*32 + rq*4) = upk(a10, a11);
    __syncthreads();
    for (int o = tid; o < 1024; o += NTH) {
        int c2 = o >> 5, r = o & 31;
        scr[o] = bias[c2] + part[c2*32 + r] + part[(32+c2)*32 + r];
    }
    // no trailing sync: epilogue reads only self-written scr entries
}

__device__ __forceinline__ void cpx(float* d, const float* s, int kc) {
    const float4* s4 = (const float4*)s; float4* d4 = (float4*)d;
#pragma unroll 4
    for (int i = threadIdx.x; i < kc*8; i += NTH) d4[i] = __ldcg(s4 + i);
}
__device__ __forceinline__ void cpx_mask(float* d, const float* s, int kc,
                                         const int* sq, int tp) {
    const float4* s4 = (const float4*)s; float4* d4 = (float4*)d;
#pragma unroll 4
    for (int i = threadIdx.x; i < kc*8; i += NTH) {
        float4 v = __ldcg(s4 + i); int r = (i & 7) * 4;
        if (tp >= sq[r+0]) v.x = 0.f; if (tp >= sq[r+1]) v.y = 0.f;
        if (tp >= sq[r+2]) v.z = 0.f; if (tp >= sq[r+3]) v.w = 0.f;
        d4[i] = v;
    }
}
__device__ __forceinline__ void cpt4(float* d, const float* s, int rs, int K) {
    int K4 = K >> 2;
#pragma unroll 4
    for (int i = threadIdx.x; i < K4*BR; i += NTH) {
        int kq = i % K4, r = i / K4;
        float4 v = *(const float4*)(s + (size_t)r*rs + kq*4);
        d[(kq*4+0)*32+r]=v.x; d[(kq*4+1)*32+r]=v.y;
        d[(kq*4+2)*32+r]=v.z; d[(kq*4+3)*32+r]=v.w;
    }
}
__device__ __forceinline__ void cpt2(float* d, const float* s, int rs, int K) {
    int K2 = K >> 1;
#pragma unroll 4
    for (int i = threadIdx.x; i < K2*BR; i += NTH) {
        int kq = i % K2, r = i / K2;
        float2 v = *(const float2*)(s + (size_t)r*rs + kq*2);
        d[(kq*2+0)*32+r]=v.x; d[(kq*2+1)*32+r]=v.y;
    }
}
__device__ __forceinline__ void ldT(float* d,int ldw,int K,const float* s,int N,int c0,int nc){
    for (int i = threadIdx.x; i < nc*ldw; i += NTH) {
        int c = i / ldw, k = i % ldw;
        d[i] = (k < K) ? s[k*N + c0 + c] : 0.f;
    }
}
__device__ __forceinline__ void ldN(float* d,int ldw,int K,const float* s,int c0,int nc){
    for (int i = threadIdx.x; i < nc*ldw; i += NTH) {
        int c = i / ldw, k = i % ldw;
        d[i] = (k < K) ? s[(c0+c)*K + k] : 0.f;
    }
}
__device__ __forceinline__ void ldRZ(float* d,int ldw,const float* wih,int Kx,
                                     const float* whh,int ct){
    for (int i = threadIdx.x; i < 16*ldw; i += NTH) {
        int c = i / ldw, k = i % ldw;
        int j = (c < 8) ? ct*8 + c : 128 + ct*8 + (c - 8);
        d[i] = (k < Kx) ? wih[j*Kx + k] : ((k < Kx+128) ? whh[j*128 + (k-Kx)] : 0.f);
    }
}
__device__ __forceinline__ float sigf(float x){ return 1.f/(1.f+expf(-x)); }

__global__ void dynarnn_init() { if (threadIdx.x < NG) g_ctr[threadIdx.x] = 0u; }

__global__ void __launch_bounds__(NTH,1)
dynarnn_main(const float* __restrict__ obp, const float* __restrict__ acp,
             const float* __restrict__ noisep, const float* __restrict__ prevp,
             const int* __restrict__ seqp,
             const float* __restrict__ Wih0, const float* __restrict__ Whh0,
             const float* __restrict__ bih0, const float* __restrict__ bhh0,
             const float* __restrict__ Wih1, const float* __restrict__ Whh1,
             const float* __restrict__ bih1, const float* __restrict__ bhh1,
             const float* __restrict__ Wt1p, const float* __restrict__ bt1p,
             const float* __restrict__ Wt2p, const float* __restrict__ bt2p,
             const float* __restrict__ Wd1p, const float* __restrict__ bd1p,
             const float* __restrict__ Wmup, const float* __restrict__ bmup,
             const float* __restrict__ Wsdp, const float* __restrict__ bsdp,
             float* __restrict__ out)
{
    extern __shared__ float sm[];
    const int tid = threadIdx.x;
    const int g = blockIdx.x >> 4, ct = blockIdx.x & 15;
    float *wt1 = sm+O_WT1, *wt2 = sm+O_WT2, *wms = sm+O_WMS, *wd = sm+O_WD;
    float *wrz0 = sm+O_WRZ0, *win0 = sm+O_WIN0, *whn0 = sm+O_WHN0;
    float *wrz1 = sm+O_WRZ1, *win1 = sm+O_WIN1, *whn1 = sm+O_WHN1;
    float *b1 = sm+O_B1, *b2 = sm+O_B2, *bS3 = sm+O_BS3, *bS4 = sm+O_BS4;
    float *bd = sm+O_BD, *bms = sm+O_BMS;
    float *sX1 = sm+O_X1, *sA = sm+O_A, *sAct = sm+O_ACT, *sX4 = sm+O_X4;
    float *part = sm+O_PART, *scr = sm+O_SCR;
    int *sseq = (int*)(sm+O_SEQ);

    ldT(wt1, 75, 74, Wt1p, 256, ct*16, 16);
    ldT(wt2, 257, 256, Wt2p, 64, ct*4, 4);
    ldT(wms, 257, 256, Wmup, 64, ct*4, 4);
    ldT(wms + 4*257, 257, 256, Wsdp, 64, ct*4, 4);
    // Wd1 rows permuted so S5 act = [ob|nos|ac|out] reuses S3's buffer
    for (int i = tid; i < 16*267; i += NTH) {
        int c = i / 267, k = i % 267;
        int ko = (k < 64) ? 192 + k : (k < 128) ? 64 + k :
                 (k < 138) ? 128 + k : (k < 266) ? k - 138 : -1;
        wd[i] = (ko >= 0) ? Wd1p[ko*256 + ct*16 + c] : 0.f;
    }
    ldRZ(wrz0, 267, Wih0, 138, Whh0, ct);
    ldRZ(wrz1, 257, Wih1, 128, Whh1, ct);
    ldN(win0, 139, 138, Wih0, 256 + ct*8, 8);
    ldN(whn0, 129, 128, Whh0, 256 + ct*8, 8);
    ldN(win1, 129, 128, Wih1, 256 + ct*8, 8);
    ldN(whn1, 129, 128, Whh1, 256 + ct*8, 8);
    if (tid < 16) {
        b1[tid] = bt1p[ct*16 + tid]; bd[tid] = bd1p[ct*16 + tid];
        int j = (tid < 8) ? ct*8 + tid : 128 + ct*8 + tid - 8;
        bS3[tid] = bih0[j] + bhh0[j]; bS4[tid] = bih1[j] + bhh1[j];
    } else if (tid < 32) {
        int q = tid - 16, j = 256 + ct*8 + (q & 7);
        if (q < 8) { bS3[tid] = bih0[j]; bS4[tid] = bih1[j]; }
        else       { bS3[tid] = bhh0[j]; bS4[tid] = bhh1[j]; }
    }
    if (tid < 4) { b2[tid] = bt2p[ct*4+tid]; bms[tid] = bmup[ct*4+tid]; bms[4+tid] = bsdp[ct*4+tid]; }
    if (tid < BR) sseq[tid] = seqp[g*BR + tid];
    for (int i = tid; i < 8*32; i += NTH) {
        int kk = i >> 5, r = i & 31, k = ct*8 + kk;
        const float* pv = prevp + (size_t)(g*BR + r) * 320;
        g_NH0[0][g][k*32 + r] = pv[k];
        g_NH1[0][g][k*32 + r] = pv[128 + k];
        if (kk < 4) { int k2 = ct*4 + kk; g_OBS[g][k2*32 + r] = pv[256 + k2]; }
    }
    unsigned nb = 1;
    bar_arrive(g); bar_wait(g, GS*nb); nb++;

    for (int t = 0; t < TT; t++) {
        float* nh0rd = g_NH0[t&1][g];       float* nh0wr = g_NH0[(t&1)^1][g];
        float* nh1rd = g_NH1[t&1][g];       float* nh1wr = g_NH1[(t&1)^1][g];
        const float* obT = obp + (size_t)g*BR*TT*64 + (size_t)t*64;
        const float* acT = acp + (size_t)g*BR*TT*10 + (size_t)t*10;
        // early noise prefetch (register-resident until S6)
        float eps = 0.f;
        if (tid < 128) {
            size_t b = (size_t)(g*BR + (tid & 31));
            eps = __ldg(noisep + (b*TT + t)*64 + ct*4 + (tid >> 5));
        }
        // S1: a = tanh([obs, ac] @ Wt1 + bt1)
        cpx(sX1, g_OBS[g], 64);
        cpt2(sX1 + 64*32, acT, TT*10, 10);
        mv<8,2,4,1>(wt1, 75, 74, sX1, b1, part, g_A[g] + ct*16*32);
        bar_arrive(g);
        // overlap barrier wait with prefetches for S3/S4
        cpt4(sAct, obT, TT*64, 64);
        cpt2(sAct + 128*32, acT, TT*10, 10);
        cpx_mask(sAct + 138*32, nh0rd, 128, sseq, t - 1);   // h0m
        cpx(sX4 + 128*32, nh1rd, 128);                      // h1m
        bar_wait(g, GS*nb); nb++;
        // S2: nos = a @ Wt2 + bt2
        cpx(sA, g_A[g], 256);
        mv<2,2,16,0>(wt2, 257, 256, sA, b2, part, g_NOS[g] + ct*4*32);
        bar_arrive(g); bar_wait(g, GS*nb); nb++;
        // S3: GRU0
        cpx(sAct + 64*32, g_NOS[g], 64);
        grudot(wrz0, 267, win0, 139, whn0, 138, sAct, bS3, part, scr);
        float hm3; int cg3; size_t bb;
        {
            int c = tid >> 5, r = tid & 31; cg3 = ct*8 + c;
            float rg = sigf(scr[c*32 + r]);
            float zg = sigf(scr[(8+c)*32 + r]);
            float ng = tanhf(scr[(16+c)*32 + r] + rg * scr[(24+c)*32 + r]);
            float hp = sAct[(138 + cg3)*32 + r];
            float nh = (1.f - zg)*ng + zg*hp;
            nh0wr[cg3*32 + r] = nh;
            hm3 = (t < sseq[r]) ? nh : 0.f;
            bb = (size_t)(g*BR + r);
        }
        bar_arrive(g);
        out[ORETS + (bb*TT + t)*320 + cg3] = hm3;
        if (t == TT-1) out[OFIN + bb*320 + cg3] = hm3;
        bar_wait(g, GS*nb); nb++;
        // S4: GRU1
        cpx(sX4, nh0wr, 128);
        grudot(wrz1, 257, win1, 129, whn1, 128, sX4, bS4, part, scr);
        float hm4;
        {
            int c = tid >> 5, r = tid & 31;
            float rg = sigf(scr[c*32 + r]);
            float zg = sigf(scr[(8+c)*32 + r]);
            float ng = tanhf(scr[(16+c)*32 + r] + rg * scr[(24+c)*32 + r]);
            float hp = sX4[(128 + cg3)*32 + r];
            float nh = (1.f - zg)*ng + zg*hp;
            hm4 = (t < sseq[r]) ? nh : 0.f;
            nh1wr[cg3*32 + r] = hm4;
        }
        bar_arrive(g);
        out[ORETS + (bb*TT + t)*320 + 128 + cg3] = hm4;
        if (t == TT-1) out[OFIN + bb*320 + 128 + cg3] = hm4;
        bar_wait(g, GS*nb); nb++;
        // S5: hdec = tanh([ob|nos|ac|out] @ Wd1perm + bd1)
        cpx(sAct + 138*32, nh1wr, 128);
        mv<8,2,4,1>(wd, 267, 266, sAct, bd, part, g_HD[g] + ct*16*32);
        bar_arrive(g); bar_wait(g, GS*nb); nb++;
        // S6: mu/std/ob_sim
        cpx(sA, g_HD[g], 256);
        mv<4,2,8,0>(wms, 257, 256, sA, bms, part, scr);
        float mu = 0.f, sd = 0.f, obs = 0.f; int cgl = 0;
        if (tid < 128) {
            int c = tid >> 5, r = tid & 31; cgl = ct*4 + c;
            mu = scr[c*32 + r];
            float sv = scr[(4+c)*32 + r];
            sd = fmaxf(sv, 0.f) + log1pf(expf(-fabsf(sv))) + 1e-4f;
            obs = fmaf(sd, eps, mu);
            g_OBS[g][cgl*32 + r] = obs;
        }
        bar_arrive(g);
        if (tid < 128) {
            size_t b = (size_t)(g*BR + (tid & 31));
            out[OMUS  + (b*TT + t)*64 + cgl] = mu;
            out[OSTDS + (b*TT + t)*64 + cgl] = sd;
            out[ORETS + (b*TT + t)*320 + 256 + cgl] = obs;
            if (t == TT-1) out[OFIN + b*320 + 256 + cgl] = obs;
        }
        bar_wait(g, GS*nb); nb++;
    }
}

extern "C" void kernel_launch(void* const* d_in, const int* in_sizes, int n_in,
                              void* d_out, int out_size) {
    cudaFuncSetAttribute(dynarnn_main, cudaFuncAttributeMaxDynamicSharedMemorySize, SMEM_BYTES);
    dynarnn_init<<<1, 32>>>();
    dynarnn_main<<<NG*GS, NTH, SMEM_BYTES>>>(
        (const float*)d_in[0], (const float*)d_in[1], (const float*)d_in[2],
        (const float*)d_in[3], (const int*)d_in[4],
        (const float*)d_in[5], (const float*)d_in[6], (const float*)d_in[7],
        (const float*)d_in[8], (const float*)d_in[9], (const float*)d_in[10],
        (const float*)d_in[11], (const float*)d_in[12],
        (const float*)d_in[13], (const float*)d_in[14], (const float*)d_in[15],
        (const float*)d_in[16], (const float*)d_in[17], (const float*)d_in[18],
        (const float*)d_in[19], (const float*)d_in[20], (const float*)d_in[21],
        (const float*)d_in[22], (float*)d_out);
}